// round 15
// baseline (speedup 1.0000x reference)
#include <cuda_runtime.h>
#include <cuda_fp16.h>
#include <math.h>
#include <stdint.h>

#define B_    32
#define CIN   96
#define COUT  96
#define HID   576
#define E_    8
#define HW    3136
#define WD    56
#define EPS   1e-5f

#define AST 104                 // A smem stride (halves)
#define BST 72                  // expand B smem stride (halves), trans ldsm conflict-free
#define PBST 136                // proj B smem stride (halves)
#define ASZ (96 * AST * 2)      // 19968 B
#define BSZ (96 * BST * 2)      // 13824 B  (== 96x72 halves, doubles as epilogue bounce)
#define PBSZ (96 * PBST * 2)    // 26112 B
#define BCST 132                // proj fp32 bounce stride (floats)

// ---------------- scratch (device globals; no allocation) ----------------
__device__ __half g_xh  [(size_t)B_*CIN*HW];
__device__ __half g_yh  [(size_t)B_*HID*HW];
__device__ __half g_y2h [(size_t)B_*HID*HW];
__device__ float  g_xpool[B_*CIN];
__device__ float  g_ypool[B_*HID];
__device__ __half g_w1h [(size_t)B_*HID*CIN];  // [b][m=HID][k=CIN]
__device__ __half g_w3h [(size_t)B_*COUT*HID]; // [b][m=COUT][k=HID]
__device__ float  g_kw  [B_*HID*9];

// ---------------- asm helpers ----------------
__device__ __forceinline__ void mma_f16(float d[4], const uint32_t a[4], uint32_t b0, uint32_t b1) {
    asm volatile(
        "mma.sync.aligned.m16n8k16.row.col.f32.f16.f16.f32 "
        "{%0,%1,%2,%3}, {%4,%5,%6,%7}, {%8,%9}, {%0,%1,%2,%3};"
        : "+f"(d[0]), "+f"(d[1]), "+f"(d[2]), "+f"(d[3])
        : "r"(a[0]), "r"(a[1]), "r"(a[2]), "r"(a[3]), "r"(b0), "r"(b1));
}
__device__ __forceinline__ uint32_t smem_u32(const void* p) {
    return (uint32_t)__cvta_generic_to_shared(p);
}
__device__ __forceinline__ void cp16(uint32_t dst, const void* src) {
    asm volatile("cp.async.cg.shared.global [%0], [%1], 16;" :: "r"(dst), "l"(src) : "memory");
}
__device__ __forceinline__ void cp16z(uint32_t dst, const void* src, int zf) {
    asm volatile("cp.async.cg.shared.global [%0], [%1], 16, %2;" :: "r"(dst), "l"(src), "r"(zf) : "memory");
}
__device__ __forceinline__ void cp_commit() { asm volatile("cp.async.commit_group;" ::: "memory"); }
__device__ __forceinline__ void cp_wait0()  { asm volatile("cp.async.wait_group 0;" ::: "memory"); }
__device__ __forceinline__ void ldsm_x4(uint32_t r[4], uint32_t addr) {
    asm volatile("ldmatrix.sync.aligned.m8n8.x4.shared.b16 {%0,%1,%2,%3}, [%4];"
        : "=r"(r[0]), "=r"(r[1]), "=r"(r[2]), "=r"(r[3]) : "r"(addr));
}
__device__ __forceinline__ void ldsm_x4_t(uint32_t r[4], uint32_t addr) {
    asm volatile("ldmatrix.sync.aligned.m8n8.x4.trans.shared.b16 {%0,%1,%2,%3}, [%4];"
        : "=r"(r[0]), "=r"(r[1]), "=r"(r[2]), "=r"(r[3]) : "r"(addr));
}

// ---------------- xpool + fp16 conversion of x ----------------
__global__ void k_xpool(const float* __restrict__ x) {
    int bc = blockIdx.x;
    const float4* p = reinterpret_cast<const float4*>(x + (size_t)bc * HW);
    __half2* xo = reinterpret_cast<__half2*>(g_xh + (size_t)bc * HW);
    float s = 0.0f;
    for (int i = threadIdx.x; i < HW / 4; i += 256) {
        float4 v = p[i];
        s += (v.x + v.y) + (v.z + v.w);
        xo[2 * i]     = __floats2half2_rn(v.x, v.y);
        xo[2 * i + 1] = __floats2half2_rn(v.z, v.w);
    }
    #pragma unroll
    for (int o = 16; o > 0; o >>= 1) s += __shfl_xor_sync(0xffffffffu, s, o);
    __shared__ float sm[8];
    if ((threadIdx.x & 31) == 0) sm[threadIdx.x >> 5] = s;
    __syncthreads();
    if (threadIdx.x == 0) {
        float t = 0.0f;
        #pragma unroll
        for (int w = 0; w < 8; w++) t += sm[w];
        g_xpool[bc] = t * (1.0f / HW);
    }
}

// ---------------- mix (router computed inline; also zeros ypool) ----------------
__global__ void k_mix(const float* __restrict__ w1, const float* __restrict__ w3,
                      const float* __restrict__ wr1, const float* __restrict__ br1,
                      const float* __restrict__ wr3, const float* __restrict__ br3) {
    const int tid = threadIdx.x;
    const int i = blockIdx.x * 256 + tid;
    const int sel = blockIdx.y;
    __shared__ float rsh[B_ * E_];
    {
        int b = tid >> 3, e = tid & 7;
        const float* xp = g_xpool + b * CIN;
        const float* wr = sel ? wr3 : wr1;
        float s = sel ? br3[e] : br1[e];
        #pragma unroll 4
        for (int c = 0; c < CIN; c++) s += xp[c] * wr[e * CIN + c];
        rsh[tid] = 1.0f / (1.0f + expf(-s));
    }
    if (sel == 0 && blockIdx.x < (B_ * HID) / 256)
        g_ypool[blockIdx.x * 256 + tid] = 0.0f;
    __syncthreads();
    if (i >= HID * CIN) return;
    const float* w = sel ? w3 : w1;
    __half* o = sel ? g_w3h : g_w1h;
    float we[E_];
    #pragma unroll
    for (int e = 0; e < E_; e++) we[e] = w[(size_t)e * HID * CIN + i];
    #pragma unroll 4
    for (int b = 0; b < B_; b++) {
        const float* r = &rsh[b * E_];
        float s = 0.0f;
        #pragma unroll
        for (int e = 0; e < E_; e++) s += r[e] * we[e];
        o[(size_t)b * HID * CIN + i] = __float2half_rn(s);
    }
}

// ---------------- router2 + depthwise kernel mixing (k_mix pattern) --------------
// grid 21 x 256: routes recomputed per block (one (b,e) dot per thread),
// then each thread owns one of HID*9 indices and loops all 32 batches.
__global__ void k_route2(const float* __restrict__ wr2, const float* __restrict__ br2,
                         const float* __restrict__ w2) {
    const int tid = threadIdx.x;
    const int i = blockIdx.x * 256 + tid;     // index into HID*9 = 5184
    __shared__ float rs[B_ * E_];
    {
        int b = tid >> 3, e = tid & 7;
        const float* yp = g_ypool + b * HID;
        const float* wr = wr2 + e * HID;
        float s = 0.0f;
        #pragma unroll 4
        for (int c = 0; c < HID; c++) s += yp[c] * wr[c];
        rs[tid] = 1.0f / (1.0f + expf(-(s * (1.0f / HW) + br2[e])));
    }
    __syncthreads();
    if (i >= HID * 9) return;
    float we[E_];
    #pragma unroll
    for (int e = 0; e < E_; e++) we[e] = w2[(size_t)e * HID * 9 + i];
    #pragma unroll 4
    for (int b = 0; b < B_; b++) {
        const float* r = &rs[b * E_];
        float s = 0.0f;
        #pragma unroll
        for (int e = 0; e < E_; e++) s += r[e] * we[e];
        g_kw[b * HID * 9 + i] = s;
    }
}

// ---------------- expand GEMM: A frags register-resident, bounce epilogue --------
// grid (6,6,32): block x covers {9,8,8,8,8,8} n-tiles of 64 within one (b,m) group.
__global__ __launch_bounds__(256) void k_expand(
        const float* __restrict__ g1, const float* __restrict__ bt1,
        const float* __restrict__ m1, const float* __restrict__ v1) {
    extern __shared__ __align__(16) char smem[];
    const int b = blockIdx.z, m0 = blockIdx.y * 96;
    const int bx = blockIdx.x;
    const int nbase = bx * 8 + (bx > 0 ? 1 : 0);      // x=0: 0 (9 tiles), x=k: 8k+1
    const int ntiles = (bx == 0) ? 9 : 8;
    const uint32_t As_u = smem_u32(smem);
    float* bn = reinterpret_cast<float*>(smem + ASZ + 2 * BSZ);   // [2][96]
    const int tid = threadIdx.x, lane = tid & 31, wid = tid >> 5;
    const int wm = wid >> 2, wn = wid & 3;
    const int gID = lane >> 2, tig = lane & 3;
    const int grp = lane >> 3, rw = lane & 7;

    const __half* Ag = g_w1h + ((size_t)b * HID + m0) * CIN;
    const __half* Bg = g_xh + (size_t)b * CIN * HW;

    // stage A (96x96) + B tile 0
    for (int i = tid; i < 1152; i += 256) {
        int row = i / 12, seg = i % 12;
        cp16(As_u + (row * AST + seg * 8) * 2, Ag + (size_t)row * CIN + seg * 8);
    }
    {
        int n0 = nbase * 64;
        for (int i = tid; i < 768; i += 256) {
            int row = i >> 3, seg = i & 7;
            cp16(As_u + ASZ + (row * BST + seg * 8) * 2, Bg + (size_t)row * HW + n0 + seg * 8);
        }
    }
    cp_commit();
    if (tid < 96) {
        int m = m0 + tid;
        float sc = g1[m] * rsqrtf(v1[m] + EPS);
        bn[tid] = sc;
        bn[96 + tid] = bt1[m] - m1[m] * sc;
    }

    uint32_t afr[6][3][4];        // A fragments: [kc][mt][4] — register resident
    float ysum[3][2] = {};
    __half* yb = g_yh + (size_t)b * HID * HW;
    const uint32_t b_base = As_u + ASZ + ((grp & 1) * 8 + rw) * BST * 2
                            + (wn * 16 + (grp >> 1) * 8) * 2;

    for (int t = 0; t < ntiles; t++) {
        cp_wait0();
        __syncthreads();
        if (t == 0) {   // load all A fragments once
            #pragma unroll
            for (int kc = 0; kc < 6; kc++)
                #pragma unroll
                for (int mt = 0; mt < 3; mt++)
                    ldsm_x4(afr[kc][mt],
                            As_u + ((wm * 48 + mt * 16 + (grp & 1) * 8 + rw) * AST
                                    + kc * 16 + (grp >> 1) * 8) * 2);
        }
        if (t < ntiles - 1) {
            uint32_t bu = As_u + ASZ + ((t + 1) & 1) * BSZ;
            int n0 = (nbase + t + 1) * 64;
            for (int i = tid; i < 768; i += 256) {
                int row = i >> 3, seg = i & 7;
                cp16(bu + (row * BST + seg * 8) * 2, Bg + (size_t)row * HW + n0 + seg * 8);
            }
            cp_commit();
        }
        const uint32_t bt = b_base + (t & 1) * BSZ;
        float acc[3][2][4] = {};
        #pragma unroll
        for (int kc = 0; kc < 6; kc++) {
            uint32_t bf[4];
            ldsm_x4_t(bf, bt + (kc * 16) * BST * 2);
            #pragma unroll
            for (int mt = 0; mt < 3; mt++) {
                mma_f16(acc[mt][0], afr[kc][mt], bf[0], bf[1]);
                mma_f16(acc[mt][1], afr[kc][mt], bf[2], bf[3]);
            }
        }
        // ---- epilogue: BN/ReLU6 in regs, bounce through dead B buffer, coalesced STG
        __syncthreads();   // all warps done reading Bs[t&1]
        __half* bounce = reinterpret_cast<__half*>(smem + ASZ + (t & 1) * BSZ);
        #pragma unroll
        for (int mt = 0; mt < 3; mt++) {
            #pragma unroll
            for (int h = 0; h < 2; h++) {
                int mr = wm * 48 + mt * 16 + gID + h * 8;
                float sc = bn[mr], bi = bn[96 + mr];
                #pragma unroll
                for (int g = 0; g < 2; g++) {
                    int nl = wn * 16 + g * 8 + tig * 2;
                    float v0 = fminf(fmaxf(acc[mt][g][h * 2 + 0] * sc + bi, 0.0f), 6.0f);
                    float v1c = fminf(fmaxf(acc[mt][g][h * 2 + 1] * sc + bi, 0.0f), 6.0f);
                    *reinterpret_cast<__half2*>(&bounce[mr * BST + nl]) = __floats2half2_rn(v0, v1c);
                    ysum[mt][h] += v0 + v1c;
                }
            }
        }
        __syncthreads();   // bounce buffer fully written
        {
            int n0 = (nbase + t) * 64;
            #pragma unroll
            for (int rd = 0; rd < 3; rd++) {
                int ch = tid + rd * 256;           // 768 chunks = 96 rows x 8 x 16B
                int r = ch >> 3, c = ch & 7;
                uint4 v = *reinterpret_cast<const uint4*>(&bounce[r * BST + c * 8]);
                *reinterpret_cast<uint4*>(&yb[(size_t)(m0 + r) * HW + n0 + c * 8]) = v;
            }
        }
    }
    #pragma unroll
    for (int mt = 0; mt < 3; mt++)
        #pragma unroll
        for (int h = 0; h < 2; h++) {
            float s = ysum[mt][h];
            s += __shfl_xor_sync(0xffffffffu, s, 1);
            s += __shfl_xor_sync(0xffffffffu, s, 2);
            if (tig == 0)
                atomicAdd(&g_ypool[b * HID + m0 + wm * 48 + mt * 16 + gID + h * 8], s);
        }
}

// ---------------- depthwise 3x3 + BN2 + ReLU6 (smem-free, direct global) --------
__global__ __launch_bounds__(224) void k_dw(
        const float* __restrict__ g2, const float* __restrict__ bt2,
        const float* __restrict__ m2, const float* __restrict__ v2) {
    const int bc = blockIdx.x;
    const int ch = bc % HID;
    const int t = threadIdx.x;
    const int r = t >> 2, seg = t & 3;
    const int c0 = seg * 14;
    const int o = c0 - 2;

    const __half* yrow = g_yh + (size_t)bc * HW;
    const float* kp = g_kw + bc * 9;
    const float kw[9] = {kp[0], kp[1], kp[2], kp[3], kp[4], kp[5], kp[6], kp[7], kp[8]};
    const float sc = g2[ch] * rsqrtf(v2[ch] + EPS);
    const float bi = bt2[ch] - m2[ch] * sc;

    float acc[14] = {};
    #pragma unroll
    for (int dr = 0; dr < 3; dr++) {
        int rr = r + dr - 1;
        float v[18];
        if (rr >= 0 && rr < WD) {
            const __half* p = yrow + rr * WD;
            #pragma unroll
            for (int i = 0; i < 9; i++) {
                int col = o + 2 * i;
                if (col >= 0 && col < WD) {
                    float2 h = __half22float2(*reinterpret_cast<const __half2*>(p + col));
                    v[2 * i] = h.x; v[2 * i + 1] = h.y;
                } else { v[2 * i] = 0.0f; v[2 * i + 1] = 0.0f; }
            }
        } else {
            #pragma unroll
            for (int i = 0; i < 18; i++) v[i] = 0.0f;
        }
        const float w0 = kw[3 * dr], w1 = kw[3 * dr + 1], w2 = kw[3 * dr + 2];
        #pragma unroll
        for (int j = 0; j < 14; j++)
            acc[j] += v[j + 1] * w0 + v[j + 2] * w1 + v[j + 3] * w2;
    }

    __half2* out2 = reinterpret_cast<__half2*>(g_y2h + (size_t)bc * HW + r * WD + c0);
    #pragma unroll
    for (int j = 0; j < 7; j++) {
        float s0 = fminf(fmaxf(acc[2 * j]     * sc + bi, 0.0f), 6.0f);
        float s1 = fminf(fmaxf(acc[2 * j + 1] * sc + bi, 0.0f), 6.0f);
        out2[j] = __floats2half2_rn(s0, s1);
    }
}

// ---------------- project GEMM: N=128 tiles, K-chunks of 96, bounce epilogue -----
__global__ __launch_bounds__(256) void k_proj(const float* __restrict__ x,
        float* __restrict__ out,
        const float* __restrict__ g3, const float* __restrict__ bt3,
        const float* __restrict__ m3, const float* __restrict__ v3) {
    extern __shared__ __align__(16) char smem[];
    const int b = blockIdx.y, n0 = blockIdx.x * 128;
    const uint32_t A_u = smem_u32(smem);
    const uint32_t B_u = A_u + 2 * ASZ;
    const int tid = threadIdx.x, lane = tid & 31, wid = tid >> 5;
    const int wm = wid >> 2, wn = wid & 3;
    const int gID = lane >> 2, tig = lane & 3;
    const int grp = lane >> 3, rw = lane & 7;

    const __half* Ag = g_w3h + (size_t)b * COUT * HID;
    const __half* Bg = g_y2h + (size_t)b * HID * HW;

    auto stage = [&](int c) {
        uint32_t au = A_u + (c & 1) * ASZ;
        for (int i = tid; i < 1152; i += 256) {
            int row = i / 12, seg = i % 12;
            cp16(au + (row * AST + seg * 8) * 2, Ag + (size_t)row * HID + c * 96 + seg * 8);
        }
        uint32_t bu = B_u + (c & 1) * PBSZ;
        for (int i = tid; i < 1536; i += 256) {
            int row = i >> 4, seg = i & 15;
            int n = n0 + seg * 8;
            cp16z(bu + (row * PBST + seg * 8) * 2,
                  Bg + (size_t)(c * 96 + row) * HW + (n < HW ? n : 0), (n < HW) ? 16 : 0);
        }
    };

    stage(0);
    cp_commit();
    float acc[3][4][4] = {};
    for (int c = 0; c < 6; c++) {
        cp_wait0();
        __syncthreads();
        if (c < 5) { stage(c + 1); cp_commit(); }
        const uint32_t au = A_u + (c & 1) * ASZ;
        const uint32_t bu = B_u + (c & 1) * PBSZ;
        #pragma unroll
        for (int kc = 0; kc < 6; kc++) {
            uint32_t a[3][4];
            #pragma unroll
            for (int mt = 0; mt < 3; mt++)
                ldsm_x4(a[mt], au + ((wm * 48 + mt * 16 + (grp & 1) * 8 + rw) * AST
                                      + kc * 16 + (grp >> 1) * 8) * 2);
            uint32_t bf[2][4];
            #pragma unroll
            for (int nb = 0; nb < 2; nb++)
                ldsm_x4_t(bf[nb], bu + ((kc * 16 + (grp & 1) * 8 + rw) * PBST
                                         + wn * 32 + nb * 16 + (grp >> 1) * 8) * 2);
            #pragma unroll
            for (int mt = 0; mt < 3; mt++) {
                mma_f16(acc[mt][0], a[mt], bf[0][0], bf[0][1]);
                mma_f16(acc[mt][1], a[mt], bf[0][2], bf[0][3]);
                mma_f16(acc[mt][2], a[mt], bf[1][0], bf[1][1]);
                mma_f16(acc[mt][3], a[mt], bf[1][2], bf[1][3]);
            }
        }
    }

    // ---- bounce epilogue: BN in regs -> STS (96x132 f32) -> coalesced x add + STG
    __syncthreads();                       // all warps done with staging smem
    float* bounce = reinterpret_cast<float*>(smem);
    #pragma unroll
    for (int mt = 0; mt < 3; mt++) {
        #pragma unroll
        for (int h = 0; h < 2; h++) {
            int m = wm * 48 + mt * 16 + gID + h * 8;
            float sc = g3[m] * rsqrtf(v3[m] + EPS);
            float bi = bt3[m] - m3[m] * sc;
            #pragma unroll
            for (int nt = 0; nt < 4; nt++) {
                int col = wn * 32 + nt * 8 + tig * 2;
                bounce[m * BCST + col]     = acc[mt][nt][h * 2 + 0] * sc + bi;
                bounce[m * BCST + col + 1] = acc[mt][nt][h * 2 + 1] * sc + bi;
            }
        }
    }
    __syncthreads();
    {
        const float* xb = x + (size_t)b * CIN * HW;
        float* ob = out + (size_t)b * COUT * HW;
        #pragma unroll
        for (int rd = 0; rd < 12; rd++) {
            int idx = tid + rd * 256;          // 3072 chunks = 96 rows x 32 x 4 floats
            int r = idx >> 5, c4 = (idx & 31) * 4;
            int n = n0 + c4;
            if (n < HW) {
                float4 v = *reinterpret_cast<const float4*>(&bounce[r * BCST + c4]);
                float4 xv = *reinterpret_cast<const float4*>(&xb[(size_t)r * HW + n]);
                v.x += xv.x; v.y += xv.y; v.z += xv.z; v.w += xv.w;
                *reinterpret_cast<float4*>(&ob[(size_t)r * HW + n]) = v;
            }
        }
    }
}

// ---------------- launcher ----------------
extern "C" void kernel_launch(void* const* d_in, const int* in_sizes, int n_in,
                              void* d_out, int out_size) {
    const float* x    = (const float*)d_in[0];
    const float* w_r1 = (const float*)d_in[1];
    const float* b_r1 = (const float*)d_in[2];
    const float* w1   = (const float*)d_in[3];
    const float* g1   = (const float*)d_in[4];
    const float* bt1  = (const float*)d_in[5];
    const float* m1   = (const float*)d_in[6];
    const float* v1   = (const float*)d_in[7];
    const float* w_r2 = (const float*)d_in[8];
    const float* b_r2 = (const float*)d_in[9];
    const float* w2   = (const float*)d_in[10];
    const float* g2   = (const float*)d_in[11];
    const float* bt2  = (const float*)d_in[12];
    const float* m2   = (const float*)d_in[13];
    const float* v2   = (const float*)d_in[14];
    const float* w3   = (const float*)d_in[15];
    const float* g3   = (const float*)d_in[16];
    const float* bt3  = (const float*)d_in[17];
    const float* m3   = (const float*)d_in[18];
    const float* v3   = (const float*)d_in[19];
    const float* w_r3 = (const float*)d_in[20];
    const float* b_r3 = (const float*)d_in[21];
    float* out = (float*)d_out;

    static int attr_done = 0;
    if (!attr_done) {
        cudaFuncSetAttribute(k_expand, cudaFuncAttributeMaxDynamicSharedMemorySize,
                             ASZ + 2 * BSZ + 96 * 2 * (int)sizeof(float));
        cudaFuncSetAttribute(k_proj, cudaFuncAttributeMaxDynamicSharedMemorySize,
                             2 * ASZ + 2 * PBSZ);
        attr_done = 1;
    }

    k_xpool<<<B_ * CIN, 256>>>(x);
    k_mix<<<dim3(216, 2), 256>>>(w1, w3, w_r1, b_r1, w_r3, b_r3);
    k_expand<<<dim3(6, 6, B_), 256, ASZ + 2 * BSZ + 96 * 2 * sizeof(float)>>>(g1, bt1, m1, v1);
    k_route2<<<(HID * 9 + 255) / 256, 256>>>(w_r2, b_r2, w2);
    k_dw<<<B_ * HID, 224>>>(g2, bt2, m2, v2);
    k_proj<<<dim3(25, B_), 256, 2 * ASZ + 2 * PBSZ>>>(x, out, g3, bt3, m3, v3);
}

// round 16
// speedup vs baseline: 1.0007x; 1.0007x over previous
#include <cuda_runtime.h>
#include <cuda_fp16.h>
#include <math.h>
#include <stdint.h>

#define B_    32
#define CIN   96
#define COUT  96
#define HID   576
#define E_    8
#define HW    3136
#define WD    56
#define EPS   1e-5f

#define AST 104                 // A smem stride (halves)
#define BST 72                  // expand B smem stride (halves), trans ldsm conflict-free
#define PBST 136                // proj B smem stride (halves)
#define ASZ (96 * AST * 2)      // 19968 B
#define BSZ (96 * BST * 2)      // 13824 B  (== 96x72 halves, doubles as epilogue bounce)
#define PBSZ (96 * PBST * 2)    // 26112 B
#define BCST 132                // proj fp32 bounce stride (floats)

// ---------------- scratch (device globals; no allocation) ----------------
__device__ __half g_xh  [(size_t)B_*CIN*HW];
__device__ __half g_yh  [(size_t)B_*HID*HW];
__device__ __half g_y2h [(size_t)B_*HID*HW];
__device__ float  g_xpool[B_*CIN];
__device__ float  g_ypool[B_*HID];
__device__ float  g_r2  [B_*E_];
__device__ __half g_w1h [(size_t)B_*HID*CIN];  // [b][m=HID][k=CIN]
__device__ __half g_w3h [(size_t)B_*COUT*HID]; // [b][m=COUT][k=HID]

// ---------------- asm helpers ----------------
__device__ __forceinline__ void mma_f16(float d[4], const uint32_t a[4], uint32_t b0, uint32_t b1) {
    asm volatile(
        "mma.sync.aligned.m16n8k16.row.col.f32.f16.f16.f32 "
        "{%0,%1,%2,%3}, {%4,%5,%6,%7}, {%8,%9}, {%0,%1,%2,%3};"
        : "+f"(d[0]), "+f"(d[1]), "+f"(d[2]), "+f"(d[3])
        : "r"(a[0]), "r"(a[1]), "r"(a[2]), "r"(a[3]), "r"(b0), "r"(b1));
}
__device__ __forceinline__ uint32_t smem_u32(const void* p) {
    return (uint32_t)__cvta_generic_to_shared(p);
}
__device__ __forceinline__ void cp16(uint32_t dst, const void* src) {
    asm volatile("cp.async.cg.shared.global [%0], [%1], 16;" :: "r"(dst), "l"(src) : "memory");
}
__device__ __forceinline__ void cp16z(uint32_t dst, const void* src, int zf) {
    asm volatile("cp.async.cg.shared.global [%0], [%1], 16, %2;" :: "r"(dst), "l"(src), "r"(zf) : "memory");
}
__device__ __forceinline__ void cp_commit() { asm volatile("cp.async.commit_group;" ::: "memory"); }
__device__ __forceinline__ void cp_wait0()  { asm volatile("cp.async.wait_group 0;" ::: "memory"); }
__device__ __forceinline__ void ldsm_x4(uint32_t r[4], uint32_t addr) {
    asm volatile("ldmatrix.sync.aligned.m8n8.x4.shared.b16 {%0,%1,%2,%3}, [%4];"
        : "=r"(r[0]), "=r"(r[1]), "=r"(r[2]), "=r"(r[3]) : "r"(addr));
}
__device__ __forceinline__ void ldsm_x4_t(uint32_t r[4], uint32_t addr) {
    asm volatile("ldmatrix.sync.aligned.m8n8.x4.trans.shared.b16 {%0,%1,%2,%3}, [%4];"
        : "=r"(r[0]), "=r"(r[1]), "=r"(r[2]), "=r"(r[3]) : "r"(addr));
}

// ---------------- xpool + fp16 conversion of x ----------------
__global__ void k_xpool(const float* __restrict__ x) {
    int bc = blockIdx.x;
    const float4* p = reinterpret_cast<const float4*>(x + (size_t)bc * HW);
    __half2* xo = reinterpret_cast<__half2*>(g_xh + (size_t)bc * HW);
    float s = 0.0f;
    for (int i = threadIdx.x; i < HW / 4; i += 256) {
        float4 v = p[i];
        s += (v.x + v.y) + (v.z + v.w);
        xo[2 * i]     = __floats2half2_rn(v.x, v.y);
        xo[2 * i + 1] = __floats2half2_rn(v.z, v.w);
    }
    #pragma unroll
    for (int o = 16; o > 0; o >>= 1) s += __shfl_xor_sync(0xffffffffu, s, o);
    __shared__ float sm[8];
    if ((threadIdx.x & 31) == 0) sm[threadIdx.x >> 5] = s;
    __syncthreads();
    if (threadIdx.x == 0) {
        float t = 0.0f;
        #pragma unroll
        for (int w = 0; w < 8; w++) t += sm[w];
        g_xpool[bc] = t * (1.0f / HW);
    }
}

// ---------------- mix (router computed inline; also zeros ypool) ----------------
__global__ void k_mix(const float* __restrict__ w1, const float* __restrict__ w3,
                      const float* __restrict__ wr1, const float* __restrict__ br1,
                      const float* __restrict__ wr3, const float* __restrict__ br3) {
    const int tid = threadIdx.x;
    const int i = blockIdx.x * 256 + tid;
    const int sel = blockIdx.y;
    __shared__ float rsh[B_ * E_];
    {
        int b = tid >> 3, e = tid & 7;
        const float* xp = g_xpool + b * CIN;
        const float* wr = sel ? wr3 : wr1;
        float s = sel ? br3[e] : br1[e];
        #pragma unroll 4
        for (int c = 0; c < CIN; c++) s += xp[c] * wr[e * CIN + c];
        rsh[tid] = 1.0f / (1.0f + expf(-s));
    }
    if (sel == 0 && blockIdx.x < (B_ * HID) / 256)
        g_ypool[blockIdx.x * 256 + tid] = 0.0f;
    __syncthreads();
    if (i >= HID * CIN) return;
    const float* w = sel ? w3 : w1;
    __half* o = sel ? g_w3h : g_w1h;
    float we[E_];
    #pragma unroll
    for (int e = 0; e < E_; e++) we[e] = w[(size_t)e * HID * CIN + i];
    #pragma unroll 4
    for (int b = 0; b < B_; b++) {
        const float* r = &rsh[b * E_];
        float s = 0.0f;
        #pragma unroll
        for (int e = 0; e < E_; e++) s += r[e] * we[e];
        o[(size_t)b * HID * CIN + i] = __float2half_rn(s);
    }
}

// ---------------- router2: warp-per-expert sigmoid routes ----------------
__global__ void k_r2(const float* __restrict__ wr2, const float* __restrict__ br2) {
    int b = blockIdx.x;
    int e = threadIdx.x >> 5, lane = threadIdx.x & 31;
    const float* yp = g_ypool + b * HID;
    float s = 0.0f;
    for (int c = lane; c < HID; c += 32) s += yp[c] * wr2[e * HID + c];
    #pragma unroll
    for (int o = 16; o > 0; o >>= 1) s += __shfl_xor_sync(0xffffffffu, s, o);
    if (lane == 0)
        g_r2[b * E_ + e] = 1.0f / (1.0f + expf(-(s * (1.0f / HW) + br2[e])));
}

// ---------------- expand GEMM: A frags register-resident, bounce epilogue --------
// grid (6,6,32): block x covers {9,8,8,8,8,8} n-tiles of 64 within one (b,m) group.
__global__ __launch_bounds__(256) void k_expand(
        const float* __restrict__ g1, const float* __restrict__ bt1,
        const float* __restrict__ m1, const float* __restrict__ v1) {
    extern __shared__ __align__(16) char smem[];
    const int b = blockIdx.z, m0 = blockIdx.y * 96;
    const int bx = blockIdx.x;
    const int nbase = bx * 8 + (bx > 0 ? 1 : 0);      // x=0: 0 (9 tiles), x=k: 8k+1
    const int ntiles = (bx == 0) ? 9 : 8;
    const uint32_t As_u = smem_u32(smem);
    float* bn = reinterpret_cast<float*>(smem + ASZ + 2 * BSZ);   // [2][96]
    const int tid = threadIdx.x, lane = tid & 31, wid = tid >> 5;
    const int wm = wid >> 2, wn = wid & 3;
    const int gID = lane >> 2, tig = lane & 3;
    const int grp = lane >> 3, rw = lane & 7;

    const __half* Ag = g_w1h + ((size_t)b * HID + m0) * CIN;
    const __half* Bg = g_xh + (size_t)b * CIN * HW;

    // stage A (96x96) + B tile 0
    for (int i = tid; i < 1152; i += 256) {
        int row = i / 12, seg = i % 12;
        cp16(As_u + (row * AST + seg * 8) * 2, Ag + (size_t)row * CIN + seg * 8);
    }
    {
        int n0 = nbase * 64;
        for (int i = tid; i < 768; i += 256) {
            int row = i >> 3, seg = i & 7;
            cp16(As_u + ASZ + (row * BST + seg * 8) * 2, Bg + (size_t)row * HW + n0 + seg * 8);
        }
    }
    cp_commit();
    if (tid < 96) {
        int m = m0 + tid;
        float sc = g1[m] * rsqrtf(v1[m] + EPS);
        bn[tid] = sc;
        bn[96 + tid] = bt1[m] - m1[m] * sc;
    }

    uint32_t afr[6][3][4];        // A fragments: [kc][mt][4] — register resident
    float ysum[3][2] = {};
    __half* yb = g_yh + (size_t)b * HID * HW;
    const uint32_t b_base = As_u + ASZ + ((grp & 1) * 8 + rw) * BST * 2
                            + (wn * 16 + (grp >> 1) * 8) * 2;

    for (int t = 0; t < ntiles; t++) {
        cp_wait0();
        __syncthreads();
        if (t == 0) {   // load all A fragments once
            #pragma unroll
            for (int kc = 0; kc < 6; kc++)
                #pragma unroll
                for (int mt = 0; mt < 3; mt++)
                    ldsm_x4(afr[kc][mt],
                            As_u + ((wm * 48 + mt * 16 + (grp & 1) * 8 + rw) * AST
                                    + kc * 16 + (grp >> 1) * 8) * 2);
        }
        if (t < ntiles - 1) {
            uint32_t bu = As_u + ASZ + ((t + 1) & 1) * BSZ;
            int n0 = (nbase + t + 1) * 64;
            for (int i = tid; i < 768; i += 256) {
                int row = i >> 3, seg = i & 7;
                cp16(bu + (row * BST + seg * 8) * 2, Bg + (size_t)row * HW + n0 + seg * 8);
            }
            cp_commit();
        }
        const uint32_t bt = b_base + (t & 1) * BSZ;
        float acc[3][2][4] = {};
        #pragma unroll
        for (int kc = 0; kc < 6; kc++) {
            uint32_t bf[4];
            ldsm_x4_t(bf, bt + (kc * 16) * BST * 2);
            #pragma unroll
            for (int mt = 0; mt < 3; mt++) {
                mma_f16(acc[mt][0], afr[kc][mt], bf[0], bf[1]);
                mma_f16(acc[mt][1], afr[kc][mt], bf[2], bf[3]);
            }
        }
        // ---- epilogue: BN/ReLU6 in regs, bounce through dead B buffer, coalesced STG
        __syncthreads();   // all warps done reading Bs[t&1]
        __half* bounce = reinterpret_cast<__half*>(smem + ASZ + (t & 1) * BSZ);
        #pragma unroll
        for (int mt = 0; mt < 3; mt++) {
            #pragma unroll
            for (int h = 0; h < 2; h++) {
                int mr = wm * 48 + mt * 16 + gID + h * 8;
                float sc = bn[mr], bi = bn[96 + mr];
                #pragma unroll
                for (int g = 0; g < 2; g++) {
                    int nl = wn * 16 + g * 8 + tig * 2;
                    float v0 = fminf(fmaxf(acc[mt][g][h * 2 + 0] * sc + bi, 0.0f), 6.0f);
                    float v1c = fminf(fmaxf(acc[mt][g][h * 2 + 1] * sc + bi, 0.0f), 6.0f);
                    *reinterpret_cast<__half2*>(&bounce[mr * BST + nl]) = __floats2half2_rn(v0, v1c);
                    ysum[mt][h] += v0 + v1c;
                }
            }
        }
        __syncthreads();   // bounce buffer fully written
        {
            int n0 = (nbase + t) * 64;
            #pragma unroll
            for (int rd = 0; rd < 3; rd++) {
                int ch = tid + rd * 256;           // 768 chunks = 96 rows x 8 x 16B
                int r = ch >> 3, c = ch & 7;
                uint4 v = *reinterpret_cast<const uint4*>(&bounce[r * BST + c * 8]);
                *reinterpret_cast<uint4*>(&yb[(size_t)(m0 + r) * HW + n0 + c * 8]) = v;
            }
        }
    }
    #pragma unroll
    for (int mt = 0; mt < 3; mt++)
        #pragma unroll
        for (int h = 0; h < 2; h++) {
            float s = ysum[mt][h];
            s += __shfl_xor_sync(0xffffffffu, s, 1);
            s += __shfl_xor_sync(0xffffffffu, s, 2);
            if (tig == 0)
                atomicAdd(&g_ypool[b * HID + m0 + wm * 48 + mt * 16 + gID + h * 8], s);
        }
}

// ---------------- depthwise 3x3 + BN2 + ReLU6 (kernel mix fused inline) ---------
__global__ __launch_bounds__(224) void k_dw(
        const float* __restrict__ w2,
        const float* __restrict__ g2, const float* __restrict__ bt2,
        const float* __restrict__ m2, const float* __restrict__ v2) {
    const int bc = blockIdx.x;
    const int b = bc / HID;
    const int ch = bc % HID;
    const int t = threadIdx.x;
    const int r = t >> 2, seg = t & 3;
    const int c0 = seg * 14;
    const int o = c0 - 2;

    // mix the 9 depthwise taps inline (uniform loads, L1/L2-hit)
    float kw[9];
    {
        const float* rp = g_r2 + b * E_;
        float r0 = rp[0], r1 = rp[1], r2 = rp[2], r3 = rp[3],
              r4 = rp[4], r5 = rp[5], r6 = rp[6], r7 = rp[7];
        #pragma unroll
        for (int j = 0; j < 9; j++) {
            const float* wp = w2 + (size_t)ch * 9 + j;
            float s = r0 * wp[0];
            s += r1 * wp[(size_t)1 * HID * 9];
            s += r2 * wp[(size_t)2 * HID * 9];
            s += r3 * wp[(size_t)3 * HID * 9];
            s += r4 * wp[(size_t)4 * HID * 9];
            s += r5 * wp[(size_t)5 * HID * 9];
            s += r6 * wp[(size_t)6 * HID * 9];
            s += r7 * wp[(size_t)7 * HID * 9];
            kw[j] = s;
        }
    }
    const float sc = g2[ch] * rsqrtf(v2[ch] + EPS);
    const float bi = bt2[ch] - m2[ch] * sc;

    const __half* yrow = g_yh + (size_t)bc * HW;
    float acc[14] = {};
    #pragma unroll
    for (int dr = 0; dr < 3; dr++) {
        int rr = r + dr - 1;
        float v[18];
        if (rr >= 0 && rr < WD) {
            const __half* p = yrow + rr * WD;
            #pragma unroll
            for (int i = 0; i < 9; i++) {
                int col = o + 2 * i;
                if (col >= 0 && col < WD) {
                    float2 h = __half22float2(*reinterpret_cast<const __half2*>(p + col));
                    v[2 * i] = h.x; v[2 * i + 1] = h.y;
                } else { v[2 * i] = 0.0f; v[2 * i + 1] = 0.0f; }
            }
        } else {
            #pragma unroll
            for (int i = 0; i < 18; i++) v[i] = 0.0f;
        }
        const float w0 = kw[3 * dr], w1 = kw[3 * dr + 1], w2v = kw[3 * dr + 2];
        #pragma unroll
        for (int j = 0; j < 14; j++)
            acc[j] += v[j + 1] * w0 + v[j + 2] * w1 + v[j + 3] * w2v;
    }

    __half2* out2 = reinterpret_cast<__half2*>(g_y2h + (size_t)bc * HW + r * WD + c0);
    #pragma unroll
    for (int j = 0; j < 7; j++) {
        float s0 = fminf(fmaxf(acc[2 * j]     * sc + bi, 0.0f), 6.0f);
        float s1 = fminf(fmaxf(acc[2 * j + 1] * sc + bi, 0.0f), 6.0f);
        out2[j] = __floats2half2_rn(s0, s1);
    }
}

// ---------------- project GEMM: N=128 tiles, K-chunks of 96, bounce epilogue -----
__global__ __launch_bounds__(256) void k_proj(const float* __restrict__ x,
        float* __restrict__ out,
        const float* __restrict__ g3, const float* __restrict__ bt3,
        const float* __restrict__ m3, const float* __restrict__ v3) {
    extern __shared__ __align__(16) char smem[];
    const int b = blockIdx.y, n0 = blockIdx.x * 128;
    const uint32_t A_u = smem_u32(smem);
    const uint32_t B_u = A_u + 2 * ASZ;
    const int tid = threadIdx.x, lane = tid & 31, wid = tid >> 5;
    const int wm = wid >> 2, wn = wid & 3;
    const int gID = lane >> 2, tig = lane & 3;
    const int grp = lane >> 3, rw = lane & 7;

    const __half* Ag = g_w3h + (size_t)b * COUT * HID;
    const __half* Bg = g_y2h + (size_t)b * HID * HW;

    auto stage = [&](int c) {
        uint32_t au = A_u + (c & 1) * ASZ;
        for (int i = tid; i < 1152; i += 256) {
            int row = i / 12, seg = i % 12;
            cp16(au + (row * AST + seg * 8) * 2, Ag + (size_t)row * HID + c * 96 + seg * 8);
        }
        uint32_t bu = B_u + (c & 1) * PBSZ;
        for (int i = tid; i < 1536; i += 256) {
            int row = i >> 4, seg = i & 15;
            int n = n0 + seg * 8;
            cp16z(bu + (row * PBST + seg * 8) * 2,
                  Bg + (size_t)(c * 96 + row) * HW + (n < HW ? n : 0), (n < HW) ? 16 : 0);
        }
    };

    stage(0);
    cp_commit();
    float acc[3][4][4] = {};
    for (int c = 0; c < 6; c++) {
        cp_wait0();
        __syncthreads();
        if (c < 5) { stage(c + 1); cp_commit(); }
        const uint32_t au = A_u + (c & 1) * ASZ;
        const uint32_t bu = B_u + (c & 1) * PBSZ;
        #pragma unroll
        for (int kc = 0; kc < 6; kc++) {
            uint32_t a[3][4];
            #pragma unroll
            for (int mt = 0; mt < 3; mt++)
                ldsm_x4(a[mt], au + ((wm * 48 + mt * 16 + (grp & 1) * 8 + rw) * AST
                                      + kc * 16 + (grp >> 1) * 8) * 2);
            uint32_t bf[2][4];
            #pragma unroll
            for (int nb = 0; nb < 2; nb++)
                ldsm_x4_t(bf[nb], bu + ((kc * 16 + (grp & 1) * 8 + rw) * PBST
                                         + wn * 32 + nb * 16 + (grp >> 1) * 8) * 2);
            #pragma unroll
            for (int mt = 0; mt < 3; mt++) {
                mma_f16(acc[mt][0], a[mt], bf[0][0], bf[0][1]);
                mma_f16(acc[mt][1], a[mt], bf[0][2], bf[0][3]);
                mma_f16(acc[mt][2], a[mt], bf[1][0], bf[1][1]);
                mma_f16(acc[mt][3], a[mt], bf[1][2], bf[1][3]);
            }
        }
    }

    // ---- bounce epilogue: BN in regs -> STS (96x132 f32) -> coalesced x add + STG
    __syncthreads();                       // all warps done with staging smem
    float* bounce = reinterpret_cast<float*>(smem);
    #pragma unroll
    for (int mt = 0; mt < 3; mt++) {
        #pragma unroll
        for (int h = 0; h < 2; h++) {
            int m = wm * 48 + mt * 16 + gID + h * 8;
            float sc = g3[m] * rsqrtf(v3[m] + EPS);
            float bi = bt3[m] - m3[m] * sc;
            #pragma unroll
            for (int nt = 0; nt < 4; nt++) {
                int col = wn * 32 + nt * 8 + tig * 2;
                bounce[m * BCST + col]     = acc[mt][nt][h * 2 + 0] * sc + bi;
                bounce[m * BCST + col + 1] = acc[mt][nt][h * 2 + 1] * sc + bi;
            }
        }
    }
    __syncthreads();
    {
        const float* xb = x + (size_t)b * CIN * HW;
        float* ob = out + (size_t)b * COUT * HW;
        #pragma unroll
        for (int rd = 0; rd < 12; rd++) {
            int idx = tid + rd * 256;          // 3072 chunks = 96 rows x 32 x 4 floats
            int r = idx >> 5, c4 = (idx & 31) * 4;
            int n = n0 + c4;
            if (n < HW) {
                float4 v = *reinterpret_cast<const float4*>(&bounce[r * BCST + c4]);
                float4 xv = *reinterpret_cast<const float4*>(&xb[(size_t)r * HW + n]);
                v.x += xv.x; v.y += xv.y; v.z += xv.z; v.w += xv.w;
                *reinterpret_cast<float4*>(&ob[(size_t)r * HW + n]) = v;
            }
        }
    }
}

// ---------------- launcher ----------------
extern "C" void kernel_launch(void* const* d_in, const int* in_sizes, int n_in,
                              void* d_out, int out_size) {
    const float* x    = (const float*)d_in[0];
    const float* w_r1 = (const float*)d_in[1];
    const float* b_r1 = (const float*)d_in[2];
    const float* w1   = (const float*)d_in[3];
    const float* g1   = (const float*)d_in[4];
    const float* bt1  = (const float*)d_in[5];
    const float* m1   = (const float*)d_in[6];
    const float* v1   = (const float*)d_in[7];
    const float* w_r2 = (const float*)d_in[8];
    const float* b_r2 = (const float*)d_in[9];
    const float* w2   = (const float*)d_in[10];
    const float* g2   = (const float*)d_in[11];
    const float* bt2  = (const float*)d_in[12];
    const float* m2   = (const float*)d_in[13];
    const float* v2   = (const float*)d_in[14];
    const float* w3   = (const float*)d_in[15];
    const float* g3   = (const float*)d_in[16];
    const float* bt3  = (const float*)d_in[17];
    const float* m3   = (const float*)d_in[18];
    const float* v3   = (const float*)d_in[19];
    const float* w_r3 = (const float*)d_in[20];
    const float* b_r3 = (const float*)d_in[21];
    float* out = (float*)d_out;

    static int attr_done = 0;
    if (!attr_done) {
        cudaFuncSetAttribute(k_expand, cudaFuncAttributeMaxDynamicSharedMemorySize,
                             ASZ + 2 * BSZ + 96 * 2 * (int)sizeof(float));
        cudaFuncSetAttribute(k_proj, cudaFuncAttributeMaxDynamicSharedMemorySize,
                             2 * ASZ + 2 * PBSZ);
        attr_done = 1;
    }

    k_xpool<<<B_ * CIN, 256>>>(x);
    k_mix<<<dim3(216, 2), 256>>>(w1, w3, w_r1, b_r1, w_r3, b_r3);
    k_expand<<<dim3(6, 6, B_), 256, ASZ + 2 * BSZ + 96 * 2 * sizeof(float)>>>(g1, bt1, m1, v1);
    k_r2<<<B_, 256>>>(w_r2, b_r2);
    k_dw<<<B_ * HID, 224>>>(w2, g2, bt2, m2, v2);
    k_proj<<<dim3(25, B_), 256, 2 * ASZ + 2 * PBSZ>>>(x, out, g3, bt3, m3, v3);
}

// round 17
// speedup vs baseline: 1.1275x; 1.1267x over previous
#include <cuda_runtime.h>
#include <cuda_fp16.h>
#include <math.h>
#include <stdint.h>

#define B_    32
#define CIN   96
#define COUT  96
#define HID   576
#define E_    8
#define HW    3136
#define WD    56
#define EPS   1e-5f

#define AST 104                 // A smem stride (halves)
#define BST 72                  // expand B smem stride (halves), trans ldsm conflict-free
#define PBST 136                // proj B smem stride (halves)
#define ASZ (96 * AST * 2)      // 19968 B
#define BSZ (96 * BST * 2)      // 13824 B  (== 96x72 halves, doubles as epilogue bounce)
#define PBSZ (96 * PBST * 2)    // 26112 B
#define BCST 132                // proj fp32 bounce stride (floats)

// ---------------- scratch (device globals; no allocation) ----------------
__device__ __half g_xh  [(size_t)B_*CIN*HW];
__device__ __half g_yh  [(size_t)B_*HID*HW];
__device__ __half g_y2h [(size_t)B_*HID*HW];
__device__ float  g_xpool[B_*CIN];
__device__ float  g_ypool[B_*HID];
__device__ __half g_w1h [(size_t)B_*HID*CIN];  // [b][m=HID][k=CIN]
__device__ __half g_w3h [(size_t)B_*COUT*HID]; // [b][m=COUT][k=HID]
__device__ float  g_kw  [B_*HID*9];

// ---------------- asm helpers ----------------
__device__ __forceinline__ void mma_f16(float d[4], const uint32_t a[4], uint32_t b0, uint32_t b1) {
    asm volatile(
        "mma.sync.aligned.m16n8k16.row.col.f32.f16.f16.f32 "
        "{%0,%1,%2,%3}, {%4,%5,%6,%7}, {%8,%9}, {%0,%1,%2,%3};"
        : "+f"(d[0]), "+f"(d[1]), "+f"(d[2]), "+f"(d[3])
        : "r"(a[0]), "r"(a[1]), "r"(a[2]), "r"(a[3]), "r"(b0), "r"(b1));
}
__device__ __forceinline__ uint32_t smem_u32(const void* p) {
    return (uint32_t)__cvta_generic_to_shared(p);
}
__device__ __forceinline__ void cp16(uint32_t dst, const void* src) {
    asm volatile("cp.async.cg.shared.global [%0], [%1], 16;" :: "r"(dst), "l"(src) : "memory");
}
__device__ __forceinline__ void cp16z(uint32_t dst, const void* src, int zf) {
    asm volatile("cp.async.cg.shared.global [%0], [%1], 16, %2;" :: "r"(dst), "l"(src), "r"(zf) : "memory");
}
__device__ __forceinline__ void cp_commit() { asm volatile("cp.async.commit_group;" ::: "memory"); }
__device__ __forceinline__ void cp_wait0()  { asm volatile("cp.async.wait_group 0;" ::: "memory"); }
__device__ __forceinline__ void ldsm_x4(uint32_t r[4], uint32_t addr) {
    asm volatile("ldmatrix.sync.aligned.m8n8.x4.shared.b16 {%0,%1,%2,%3}, [%4];"
        : "=r"(r[0]), "=r"(r[1]), "=r"(r[2]), "=r"(r[3]) : "r"(addr));
}
__device__ __forceinline__ void ldsm_x4_t(uint32_t r[4], uint32_t addr) {
    asm volatile("ldmatrix.sync.aligned.m8n8.x4.trans.shared.b16 {%0,%1,%2,%3}, [%4];"
        : "=r"(r[0]), "=r"(r[1]), "=r"(r[2]), "=r"(r[3]) : "r"(addr));
}

// ---------------- xpool + fp16 conversion of x ----------------
__global__ void k_xpool(const float* __restrict__ x) {
    int bc = blockIdx.x;
    const float4* p = reinterpret_cast<const float4*>(x + (size_t)bc * HW);
    __half2* xo = reinterpret_cast<__half2*>(g_xh + (size_t)bc * HW);
    float s = 0.0f;
    for (int i = threadIdx.x; i < HW / 4; i += 256) {
        float4 v = p[i];
        s += (v.x + v.y) + (v.z + v.w);
        xo[2 * i]     = __floats2half2_rn(v.x, v.y);
        xo[2 * i + 1] = __floats2half2_rn(v.z, v.w);
    }
    #pragma unroll
    for (int o = 16; o > 0; o >>= 1) s += __shfl_xor_sync(0xffffffffu, s, o);
    __shared__ float sm[8];
    if ((threadIdx.x & 31) == 0) sm[threadIdx.x >> 5] = s;
    __syncthreads();
    if (threadIdx.x == 0) {
        float t = 0.0f;
        #pragma unroll
        for (int w = 0; w < 8; w++) t += sm[w];
        g_xpool[bc] = t * (1.0f / HW);
    }
}

// ---------------- mix (router computed inline; also zeros ypool) ----------------
__global__ void k_mix(const float* __restrict__ w1, const float* __restrict__ w3,
                      const float* __restrict__ wr1, const float* __restrict__ br1,
                      const float* __restrict__ wr3, const float* __restrict__ br3) {
    const int tid = threadIdx.x;
    const int i = blockIdx.x * 256 + tid;
    const int sel = blockIdx.y;
    __shared__ float rsh[B_ * E_];
    {
        int b = tid >> 3, e = tid & 7;
        const float* xp = g_xpool + b * CIN;
        const float* wr = sel ? wr3 : wr1;
        float s = sel ? br3[e] : br1[e];
        #pragma unroll 4
        for (int c = 0; c < CIN; c++) s += xp[c] * wr[e * CIN + c];
        rsh[tid] = 1.0f / (1.0f + expf(-s));
    }
    if (sel == 0 && blockIdx.x < (B_ * HID) / 256)
        g_ypool[blockIdx.x * 256 + tid] = 0.0f;
    __syncthreads();
    if (i >= HID * CIN) return;
    const float* w = sel ? w3 : w1;
    __half* o = sel ? g_w3h : g_w1h;
    float we[E_];
    #pragma unroll
    for (int e = 0; e < E_; e++) we[e] = w[(size_t)e * HID * CIN + i];
    #pragma unroll 4
    for (int b = 0; b < B_; b++) {
        const float* r = &rsh[b * E_];
        float s = 0.0f;
        #pragma unroll
        for (int e = 0; e < E_; e++) s += r[e] * we[e];
        o[(size_t)b * HID * CIN + i] = __float2half_rn(s);
    }
}

// ---------------- router2 + depthwise kernel mixing, chunked ------------------
// grid (8 chunks, 32 batches): each block recomputes its batch's 8 routes
// (warp-per-expert, coalesced) then mixes its 648-index chunk of HID*9.
__global__ void k_route2(const float* __restrict__ wr2, const float* __restrict__ br2,
                         const float* __restrict__ w2) {
    const int b = blockIdx.y;
    const int chunk = blockIdx.x;
    __shared__ float rs[E_];
    int w = threadIdx.x >> 5, lane = threadIdx.x & 31;
    {
        const float* yp = g_ypool + b * HID;
        float s = 0.0f;
        for (int c = lane; c < HID; c += 32) s += yp[c] * wr2[w * HID + c];
        #pragma unroll
        for (int o = 16; o > 0; o >>= 1) s += __shfl_xor_sync(0xffffffffu, s, o);
        if (lane == 0) rs[w] = 1.0f / (1.0f + expf(-(s * (1.0f / HW) + br2[w])));
    }
    __syncthreads();
    const int i0 = chunk * 648;                 // 8 * 648 = 5184 = HID*9
    for (int i = i0 + threadIdx.x; i < i0 + 648; i += 256) {
        float s = 0.0f;
        #pragma unroll
        for (int e = 0; e < E_; e++) s += rs[e] * w2[(size_t)e * HID * 9 + i];
        g_kw[b * HID * 9 + i] = s;
    }
}

// ---------------- expand GEMM: A frags register-resident, bounce epilogue --------
// grid (6,6,32): block x covers {9,8,8,8,8,8} n-tiles of 64 within one (b,m) group.
__global__ __launch_bounds__(256) void k_expand(
        const float* __restrict__ g1, const float* __restrict__ bt1,
        const float* __restrict__ m1, const float* __restrict__ v1) {
    extern __shared__ __align__(16) char smem[];
    const int b = blockIdx.z, m0 = blockIdx.y * 96;
    const int bx = blockIdx.x;
    const int nbase = bx * 8 + (bx > 0 ? 1 : 0);      // x=0: 0 (9 tiles), x=k: 8k+1
    const int ntiles = (bx == 0) ? 9 : 8;
    const uint32_t As_u = smem_u32(smem);
    float* bn = reinterpret_cast<float*>(smem + ASZ + 2 * BSZ);   // [2][96]
    const int tid = threadIdx.x, lane = tid & 31, wid = tid >> 5;
    const int wm = wid >> 2, wn = wid & 3;
    const int gID = lane >> 2, tig = lane & 3;
    const int grp = lane >> 3, rw = lane & 7;

    const __half* Ag = g_w1h + ((size_t)b * HID + m0) * CIN;
    const __half* Bg = g_xh + (size_t)b * CIN * HW;

    // stage A (96x96) + B tile 0
    for (int i = tid; i < 1152; i += 256) {
        int row = i / 12, seg = i % 12;
        cp16(As_u + (row * AST + seg * 8) * 2, Ag + (size_t)row * CIN + seg * 8);
    }
    {
        int n0 = nbase * 64;
        for (int i = tid; i < 768; i += 256) {
            int row = i >> 3, seg = i & 7;
            cp16(As_u + ASZ + (row * BST + seg * 8) * 2, Bg + (size_t)row * HW + n0 + seg * 8);
        }
    }
    cp_commit();
    if (tid < 96) {
        int m = m0 + tid;
        float sc = g1[m] * rsqrtf(v1[m] + EPS);
        bn[tid] = sc;
        bn[96 + tid] = bt1[m] - m1[m] * sc;
    }

    uint32_t afr[6][3][4];        // A fragments: [kc][mt][4] — register resident
    float ysum[3][2] = {};
    __half* yb = g_yh + (size_t)b * HID * HW;
    const uint32_t b_base = As_u + ASZ + ((grp & 1) * 8 + rw) * BST * 2
                            + (wn * 16 + (grp >> 1) * 8) * 2;

    for (int t = 0; t < ntiles; t++) {
        cp_wait0();
        __syncthreads();
        if (t == 0) {   // load all A fragments once
            #pragma unroll
            for (int kc = 0; kc < 6; kc++)
                #pragma unroll
                for (int mt = 0; mt < 3; mt++)
                    ldsm_x4(afr[kc][mt],
                            As_u + ((wm * 48 + mt * 16 + (grp & 1) * 8 + rw) * AST
                                    + kc * 16 + (grp >> 1) * 8) * 2);
        }
        if (t < ntiles - 1) {
            uint32_t bu = As_u + ASZ + ((t + 1) & 1) * BSZ;
            int n0 = (nbase + t + 1) * 64;
            for (int i = tid; i < 768; i += 256) {
                int row = i >> 3, seg = i & 7;
                cp16(bu + (row * BST + seg * 8) * 2, Bg + (size_t)row * HW + n0 + seg * 8);
            }
            cp_commit();
        }
        const uint32_t bt = b_base + (t & 1) * BSZ;
        float acc[3][2][4] = {};
        #pragma unroll
        for (int kc = 0; kc < 6; kc++) {
            uint32_t bf[4];
            ldsm_x4_t(bf, bt + (kc * 16) * BST * 2);
            #pragma unroll
            for (int mt = 0; mt < 3; mt++) {
                mma_f16(acc[mt][0], afr[kc][mt], bf[0], bf[1]);
                mma_f16(acc[mt][1], afr[kc][mt], bf[2], bf[3]);
            }
        }
        // ---- epilogue: BN/ReLU6 in regs, bounce through dead B buffer, coalesced STG
        __syncthreads();   // all warps done reading Bs[t&1]
        __half* bounce = reinterpret_cast<__half*>(smem + ASZ + (t & 1) * BSZ);
        #pragma unroll
        for (int mt = 0; mt < 3; mt++) {
            #pragma unroll
            for (int h = 0; h < 2; h++) {
                int mr = wm * 48 + mt * 16 + gID + h * 8;
                float sc = bn[mr], bi = bn[96 + mr];
                #pragma unroll
                for (int g = 0; g < 2; g++) {
                    int nl = wn * 16 + g * 8 + tig * 2;
                    float v0 = fminf(fmaxf(acc[mt][g][h * 2 + 0] * sc + bi, 0.0f), 6.0f);
                    float v1c = fminf(fmaxf(acc[mt][g][h * 2 + 1] * sc + bi, 0.0f), 6.0f);
                    *reinterpret_cast<__half2*>(&bounce[mr * BST + nl]) = __floats2half2_rn(v0, v1c);
                    ysum[mt][h] += v0 + v1c;
                }
            }
        }
        __syncthreads();   // bounce buffer fully written
        {
            int n0 = (nbase + t) * 64;
            #pragma unroll
            for (int rd = 0; rd < 3; rd++) {
                int ch = tid + rd * 256;           // 768 chunks = 96 rows x 8 x 16B
                int r = ch >> 3, c = ch & 7;
                uint4 v = *reinterpret_cast<const uint4*>(&bounce[r * BST + c * 8]);
                *reinterpret_cast<uint4*>(&yb[(size_t)(m0 + r) * HW + n0 + c * 8]) = v;
            }
        }
    }
    #pragma unroll
    for (int mt = 0; mt < 3; mt++)
        #pragma unroll
        for (int h = 0; h < 2; h++) {
            float s = ysum[mt][h];
            s += __shfl_xor_sync(0xffffffffu, s, 1);
            s += __shfl_xor_sync(0xffffffffu, s, 2);
            if (tig == 0)
                atomicAdd(&g_ypool[b * HID + m0 + wm * 48 + mt * 16 + gID + h * 8], s);
        }
}

// ---------------- depthwise 3x3 + BN2 + ReLU6 (smem-free, direct global) --------
__global__ __launch_bounds__(224) void k_dw(
        const float* __restrict__ g2, const float* __restrict__ bt2,
        const float* __restrict__ m2, const float* __restrict__ v2) {
    const int bc = blockIdx.x;
    const int ch = bc % HID;
    const int t = threadIdx.x;
    const int r = t >> 2, seg = t & 3;
    const int c0 = seg * 14;
    const int o = c0 - 2;

    const __half* yrow = g_yh + (size_t)bc * HW;
    const float* kp = g_kw + bc * 9;
    const float kw[9] = {kp[0], kp[1], kp[2], kp[3], kp[4], kp[5], kp[6], kp[7], kp[8]};
    const float sc = g2[ch] * rsqrtf(v2[ch] + EPS);
    const float bi = bt2[ch] - m2[ch] * sc;

    float acc[14] = {};
    #pragma unroll
    for (int dr = 0; dr < 3; dr++) {
        int rr = r + dr - 1;
        float v[18];
        if (rr >= 0 && rr < WD) {
            const __half* p = yrow + rr * WD;
            #pragma unroll
            for (int i = 0; i < 9; i++) {
                int col = o + 2 * i;
                if (col >= 0 && col < WD) {
                    float2 h = __half22float2(*reinterpret_cast<const __half2*>(p + col));
                    v[2 * i] = h.x; v[2 * i + 1] = h.y;
                } else { v[2 * i] = 0.0f; v[2 * i + 1] = 0.0f; }
            }
        } else {
            #pragma unroll
            for (int i = 0; i < 18; i++) v[i] = 0.0f;
        }
        const float w0 = kw[3 * dr], w1 = kw[3 * dr + 1], w2 = kw[3 * dr + 2];
        #pragma unroll
        for (int j = 0; j < 14; j++)
            acc[j] += v[j + 1] * w0 + v[j + 2] * w1 + v[j + 3] * w2;
    }

    __half2* out2 = reinterpret_cast<__half2*>(g_y2h + (size_t)bc * HW + r * WD + c0);
    #pragma unroll
    for (int j = 0; j < 7; j++) {
        float s0 = fminf(fmaxf(acc[2 * j]     * sc + bi, 0.0f), 6.0f);
        float s1 = fminf(fmaxf(acc[2 * j + 1] * sc + bi, 0.0f), 6.0f);
        out2[j] = __floats2half2_rn(s0, s1);
    }
}

// ---------------- project GEMM: N=128 tiles, K-chunks of 96, bounce epilogue -----
__global__ __launch_bounds__(256) void k_proj(const float* __restrict__ x,
        float* __restrict__ out,
        const float* __restrict__ g3, const float* __restrict__ bt3,
        const float* __restrict__ m3, const float* __restrict__ v3) {
    extern __shared__ __align__(16) char smem[];
    const int b = blockIdx.y, n0 = blockIdx.x * 128;
    const uint32_t A_u = smem_u32(smem);
    const uint32_t B_u = A_u + 2 * ASZ;
    const int tid = threadIdx.x, lane = tid & 31, wid = tid >> 5;
    const int wm = wid >> 2, wn = wid & 3;
    const int gID = lane >> 2, tig = lane & 3;
    const int grp = lane >> 3, rw = lane & 7;

    const __half* Ag = g_w3h + (size_t)b * COUT * HID;
    const __half* Bg = g_y2h + (size_t)b * HID * HW;

    auto stage = [&](int c) {
        uint32_t au = A_u + (c & 1) * ASZ;
        for (int i = tid; i < 1152; i += 256) {
            int row = i / 12, seg = i % 12;
            cp16(au + (row * AST + seg * 8) * 2, Ag + (size_t)row * HID + c * 96 + seg * 8);
        }
        uint32_t bu = B_u + (c & 1) * PBSZ;
        for (int i = tid; i < 1536; i += 256) {
            int row = i >> 4, seg = i & 15;
            int n = n0 + seg * 8;
            cp16z(bu + (row * PBST + seg * 8) * 2,
                  Bg + (size_t)(c * 96 + row) * HW + (n < HW ? n : 0), (n < HW) ? 16 : 0);
        }
    };

    stage(0);
    cp_commit();
    float acc[3][4][4] = {};
    for (int c = 0; c < 6; c++) {
        cp_wait0();
        __syncthreads();
        if (c < 5) { stage(c + 1); cp_commit(); }
        const uint32_t au = A_u + (c & 1) * ASZ;
        const uint32_t bu = B_u + (c & 1) * PBSZ;
        #pragma unroll
        for (int kc = 0; kc < 6; kc++) {
            uint32_t a[3][4];
            #pragma unroll
            for (int mt = 0; mt < 3; mt++)
                ldsm_x4(a[mt], au + ((wm * 48 + mt * 16 + (grp & 1) * 8 + rw) * AST
                                      + kc * 16 + (grp >> 1) * 8) * 2);
            uint32_t bf[2][4];
            #pragma unroll
            for (int nb = 0; nb < 2; nb++)
                ldsm_x4_t(bf[nb], bu + ((kc * 16 + (grp & 1) * 8 + rw) * PBST
                                         + wn * 32 + nb * 16 + (grp >> 1) * 8) * 2);
            #pragma unroll
            for (int mt = 0; mt < 3; mt++) {
                mma_f16(acc[mt][0], a[mt], bf[0][0], bf[0][1]);
                mma_f16(acc[mt][1], a[mt], bf[0][2], bf[0][3]);
                mma_f16(acc[mt][2], a[mt], bf[1][0], bf[1][1]);
                mma_f16(acc[mt][3], a[mt], bf[1][2], bf[1][3]);
            }
        }
    }

    // ---- bounce epilogue: BN in regs -> STS (96x132 f32) -> coalesced x add + STG
    __syncthreads();                       // all warps done with staging smem
    float* bounce = reinterpret_cast<float*>(smem);
    #pragma unroll
    for (int mt = 0; mt < 3; mt++) {
        #pragma unroll
        for (int h = 0; h < 2; h++) {
            int m = wm * 48 + mt * 16 + gID + h * 8;
            float sc = g3[m] * rsqrtf(v3[m] + EPS);
            float bi = bt3[m] - m3[m] * sc;
            #pragma unroll
            for (int nt = 0; nt < 4; nt++) {
                int col = wn * 32 + nt * 8 + tig * 2;
                bounce[m * BCST + col]     = acc[mt][nt][h * 2 + 0] * sc + bi;
                bounce[m * BCST + col + 1] = acc[mt][nt][h * 2 + 1] * sc + bi;
            }
        }
    }
    __syncthreads();
    {
        const float* xb = x + (size_t)b * CIN * HW;
        float* ob = out + (size_t)b * COUT * HW;
        #pragma unroll
        for (int rd = 0; rd < 12; rd++) {
            int idx = tid + rd * 256;          // 3072 chunks = 96 rows x 32 x 4 floats
            int r = idx >> 5, c4 = (idx & 31) * 4;
            int n = n0 + c4;
            if (n < HW) {
                float4 v = *reinterpret_cast<const float4*>(&bounce[r * BCST + c4]);
                float4 xv = *reinterpret_cast<const float4*>(&xb[(size_t)r * HW + n]);
                v.x += xv.x; v.y += xv.y; v.z += xv.z; v.w += xv.w;
                *reinterpret_cast<float4*>(&ob[(size_t)r * HW + n]) = v;
            }
        }
    }
}

// ---------------- launcher ----------------
extern "C" void kernel_launch(void* const* d_in, const int* in_sizes, int n_in,
                              void* d_out, int out_size) {
    const float* x    = (const float*)d_in[0];
    const float* w_r1 = (const float*)d_in[1];
    const float* b_r1 = (const float*)d_in[2];
    const float* w1   = (const float*)d_in[3];
    const float* g1   = (const float*)d_in[4];
    const float* bt1  = (const float*)d_in[5];
    const float* m1   = (const float*)d_in[6];
    const float* v1   = (const float*)d_in[7];
    const float* w_r2 = (const float*)d_in[8];
    const float* b_r2 = (const float*)d_in[9];
    const float* w2   = (const float*)d_in[10];
    const float* g2   = (const float*)d_in[11];
    const float* bt2  = (const float*)d_in[12];
    const float* m2   = (const float*)d_in[13];
    const float* v2   = (const float*)d_in[14];
    const float* w3   = (const float*)d_in[15];
    const float* g3   = (const float*)d_in[16];
    const float* bt3  = (const float*)d_in[17];
    const float* m3   = (const float*)d_in[18];
    const float* v3   = (const float*)d_in[19];
    const float* w_r3 = (const float*)d_in[20];
    const float* b_r3 = (const float*)d_in[21];
    float* out = (float*)d_out;

    static int attr_done = 0;
    if (!attr_done) {
        cudaFuncSetAttribute(k_expand, cudaFuncAttributeMaxDynamicSharedMemorySize,
                             ASZ + 2 * BSZ + 96 * 2 * (int)sizeof(float));
        cudaFuncSetAttribute(k_proj, cudaFuncAttributeMaxDynamicSharedMemorySize,
                             2 * ASZ + 2 * PBSZ);
        attr_done = 1;
    }

    k_xpool<<<B_ * CIN, 256>>>(x);
    k_mix<<<dim3(216, 2), 256>>>(w1, w3, w_r1, b_r1, w_r3, b_r3);
    k_expand<<<dim3(6, 6, B_), 256, ASZ + 2 * BSZ + 96 * 2 * sizeof(float)>>>(g1, bt1, m1, v1);
    k_route2<<<dim3(8, B_), 256>>>(w_r2, b_r2, w2);
    k_dw<<<B_ * HID, 224>>>(g2, bt2, m2, v2);
    k_proj<<<dim3(25, B_), 256, 2 * ASZ + 2 * PBSZ>>>(x, out, g3, bt3, m3, v3);
}